// round 13
// baseline (speedup 1.0000x reference)
#include <cuda_runtime.h>

#define G 512
#define NVERT (G * G)

// Per vertex, the reference's last-write-wins scatter leaves exactly one face's
// angle-weighted normal. In every branch the angle weight is >= 0, so
// sign(normal_z) == sign(cross(e0, e2).z) == sign(e0x*e2y - e0y*e2x),
// which needs only the x,y channels of X. Output = (tnz >= 0) ? 0 : 1 on all
// 3 channels.
//
// Final kernel == R1: best of 9 measured variants (bench 6.56us, ncu 6.18us).
// Identical-source resubmission showed +-1.5us wallclock noise; ncu kernel
// time is pinned at ~6.4us across every restructure tried (row tiling, batch
// pairing, shfl neighbors, streaming stores, thin/fat threads, CTA resizing),
// i.e. the kernel is at its latency+overhead floor.
//
// 4 columns per thread (float4), 128 threads per row, one block per (row, batch).
__global__ void __launch_bounds__(128) vis_mask_kernel(const float* __restrict__ X,
                                                       float* __restrict__ out) {
    const int c0 = threadIdx.x << 2;   // 128 * 4 = 512 columns
    const int r  = blockIdx.x;
    const int b  = blockIdx.y;

    const float* Xx = X + (size_t)b * 3 * NVERT;
    const float* Xy = Xx + NVERT;

    // Two rows feed each output row: (r-1, r) interior; (0, 1) for r == 0.
    const int rA = (r >= 1) ? (r - 1) : 0;
    const int rB = (r >= 1) ? r : 1;

    const float4 xA = *(const float4*)(Xx + rA * G + c0);
    const float4 yA = *(const float4*)(Xy + rA * G + c0);
    const float4 xB = *(const float4*)(Xx + rB * G + c0);
    const float4 yB = *(const float4*)(Xy + rB * G + c0);

    // Left-neighbor scalars at column c0-1 (only thread 0 skips them).
    float xAm = 0.f, yAm = 0.f, xBm = 0.f, yBm = 0.f;
    if (c0 > 0) {
        xBm = Xx[rB * G + c0 - 1];
        yBm = Xy[rB * G + c0 - 1];
        if (r == 0) {
            xAm = Xx[rA * G + c0 - 1];
            yAm = Xy[rA * G + c0 - 1];
        }
    }

    const float xa[5] = {xAm, xA.x, xA.y, xA.z, xA.w};
    const float ya[5] = {yAm, yA.x, yA.y, yA.z, yA.w};
    const float xb[5] = {xBm, xB.x, xB.y, xB.z, xB.w};
    const float yb[5] = {yBm, yB.x, yB.y, yB.z, yB.w};

    float o[4];
#pragma unroll
    for (int k = 0; k < 4; k++) {
        const int c = c0 + k;
        float e0x, e0y, e2x, e2y;
        if (r >= 1) {
            if (c >= 1) {
                // v0=(r-1,c), v1=(r,c-1), v2=(r,c)
                e0x = xb[k] - xa[k + 1];  e0y = yb[k] - ya[k + 1];
                e2x = xb[k] - xb[k + 1];  e2y = yb[k] - yb[k + 1];
            } else {
                // c==0: v0=(r-1,1), v1=(r,0), v2=(r,1)
                e0x = xb[1] - xa[2];  e0y = yb[1] - ya[2];
                e2x = xb[1] - xb[2];  e2y = yb[1] - yb[2];
            }
        } else {
            if (c >= 1) {
                // r==0: v0=(0,c-1), v1=(1,c-1), v2=(0,c)
                e0x = xb[k] - xa[k];      e0y = yb[k] - ya[k];
                e2x = xb[k] - xa[k + 1];  e2y = yb[k] - ya[k + 1];
            } else {
                // (0,0): v0=(0,0), v1=(1,0), v2=(0,1)
                e0x = xb[1] - xa[1];  e0y = yb[1] - ya[1];
                e2x = xb[1] - xa[2];  e2y = yb[1] - ya[2];
            }
        }
        const float tnz = e0x * e2y - e0y * e2x;
        o[k] = (tnz >= 0.0f) ? 0.0f : 1.0f;
    }

    const float4 ov = make_float4(o[0], o[1], o[2], o[3]);
    float* ob = out + (size_t)b * 3 * NVERT + (size_t)r * G + c0;
    *(float4*)(ob)             = ov;
    *(float4*)(ob + NVERT)     = ov;
    *(float4*)(ob + 2 * NVERT) = ov;
}

extern "C" void kernel_launch(void* const* d_in, const int* in_sizes, int n_in,
                              void* d_out, int out_size) {
    const float* X = (const float*)d_in[0];   // (4, 3, 512*512) float32
    // d_in[1] = faces (int32) — implicit in the grid structure, unused.
    float* out = (float*)d_out;               // (4, 3, 512, 512) float32

    dim3 block(128, 1, 1);
    dim3 grid(G, 4, 1);
    vis_mask_kernel<<<grid, block>>>(X, out);
}

// round 14
// speedup vs baseline: 1.2632x; 1.2632x over previous
#include <cuda_runtime.h>

#define G 512
#define NVERT (G * G)

// Per vertex, the reference's last-write-wins scatter leaves exactly one face's
// angle-weighted normal. In every branch the angle weight is >= 0, so
// sign(normal_z) == sign(cross(e0, e2).z) == sign(e0x*e2y - e0y*e2x),
// which needs only the x,y channels of X. Output = (tnz >= 0) ? 0 : 1 on all
// 3 channels.
//
// FINAL kernel == R1: best of 9 measured structural variants. Identical
// source has benched 6.56 / 8.13 / 10.75 us and profiled 6.18 / 6.37 / 9.25
// us (HBM 1318 vs 908 GB/s on identical SASS) — the measurement environment
// (--clock-control none, DVFS) dominates; no structural signal remains.
//
// 4 columns per thread (float4), 128 threads per row, one block per (row, batch).
__global__ void __launch_bounds__(128) vis_mask_kernel(const float* __restrict__ X,
                                                       float* __restrict__ out) {
    const int c0 = threadIdx.x << 2;   // 128 * 4 = 512 columns
    const int r  = blockIdx.x;
    const int b  = blockIdx.y;

    const float* Xx = X + (size_t)b * 3 * NVERT;
    const float* Xy = Xx + NVERT;

    // Two rows feed each output row: (r-1, r) interior; (0, 1) for r == 0.
    const int rA = (r >= 1) ? (r - 1) : 0;
    const int rB = (r >= 1) ? r : 1;

    const float4 xA = *(const float4*)(Xx + rA * G + c0);
    const float4 yA = *(const float4*)(Xy + rA * G + c0);
    const float4 xB = *(const float4*)(Xx + rB * G + c0);
    const float4 yB = *(const float4*)(Xy + rB * G + c0);

    // Left-neighbor scalars at column c0-1 (only thread 0 skips them).
    float xAm = 0.f, yAm = 0.f, xBm = 0.f, yBm = 0.f;
    if (c0 > 0) {
        xBm = Xx[rB * G + c0 - 1];
        yBm = Xy[rB * G + c0 - 1];
        if (r == 0) {
            xAm = Xx[rA * G + c0 - 1];
            yAm = Xy[rA * G + c0 - 1];
        }
    }

    const float xa[5] = {xAm, xA.x, xA.y, xA.z, xA.w};
    const float ya[5] = {yAm, yA.x, yA.y, yA.z, yA.w};
    const float xb[5] = {xBm, xB.x, xB.y, xB.z, xB.w};
    const float yb[5] = {yBm, yB.x, yB.y, yB.z, yB.w};

    float o[4];
#pragma unroll
    for (int k = 0; k < 4; k++) {
        const int c = c0 + k;
        float e0x, e0y, e2x, e2y;
        if (r >= 1) {
            if (c >= 1) {
                // v0=(r-1,c), v1=(r,c-1), v2=(r,c)
                e0x = xb[k] - xa[k + 1];  e0y = yb[k] - ya[k + 1];
                e2x = xb[k] - xb[k + 1];  e2y = yb[k] - yb[k + 1];
            } else {
                // c==0: v0=(r-1,1), v1=(r,0), v2=(r,1)
                e0x = xb[1] - xa[2];  e0y = yb[1] - ya[2];
                e2x = xb[1] - xb[2];  e2y = yb[1] - yb[2];
            }
        } else {
            if (c >= 1) {
                // r==0: v0=(0,c-1), v1=(1,c-1), v2=(0,c)
                e0x = xb[k] - xa[k];      e0y = yb[k] - ya[k];
                e2x = xb[k] - xa[k + 1];  e2y = yb[k] - ya[k + 1];
            } else {
                // (0,0): v0=(0,0), v1=(1,0), v2=(0,1)
                e0x = xb[1] - xa[1];  e0y = yb[1] - ya[1];
                e2x = xb[1] - xa[2];  e2y = yb[1] - ya[2];
            }
        }
        const float tnz = e0x * e2y - e0y * e2x;
        o[k] = (tnz >= 0.0f) ? 0.0f : 1.0f;
    }

    const float4 ov = make_float4(o[0], o[1], o[2], o[3]);
    float* ob = out + (size_t)b * 3 * NVERT + (size_t)r * G + c0;
    *(float4*)(ob)             = ov;
    *(float4*)(ob + NVERT)     = ov;
    *(float4*)(ob + 2 * NVERT) = ov;
}

extern "C" void kernel_launch(void* const* d_in, const int* in_sizes, int n_in,
                              void* d_out, int out_size) {
    const float* X = (const float*)d_in[0];   // (4, 3, 512*512) float32
    // d_in[1] = faces (int32) — implicit in the grid structure, unused.
    float* out = (float*)d_out;               // (4, 3, 512, 512) float32

    dim3 block(128, 1, 1);
    dim3 grid(G, 4, 1);
    vis_mask_kernel<<<grid, block>>>(X, out);
}

// round 15
// speedup vs baseline: 1.6154x; 1.2788x over previous
#include <cuda_runtime.h>

#define G 512
#define NVERT (G * G)

// Per vertex, the reference's last-write-wins scatter leaves exactly one face's
// angle-weighted normal. In every branch the angle weight is >= 0, so
// sign(normal_z) == sign(cross(e0, e2).z) == sign(e0x*e2y - e0y*e2x),
// which needs only the x,y channels of X. Output = (tnz >= 0) ? 0 : 1 on all
// 3 channels.
//
// FINAL kernel == R1: best of 9 measured structural variants. Identical
// source has benched 6.56 / 8.13 / 10.75 / 8.51 us (ncu 6.18-9.25 us, HBM
// 908-1318 GB/s on identical SASS) — measurement environment noise
// (--clock-control none, DVFS, replay state) dominates; the kernel itself is
// at its latency+overhead floor doing minimum work (8 MB reads, 12 MB writes,
// no transcendentals).
//
// 4 columns per thread (float4), 128 threads per row, one block per (row, batch).
__global__ void __launch_bounds__(128) vis_mask_kernel(const float* __restrict__ X,
                                                       float* __restrict__ out) {
    const int c0 = threadIdx.x << 2;   // 128 * 4 = 512 columns
    const int r  = blockIdx.x;
    const int b  = blockIdx.y;

    const float* Xx = X + (size_t)b * 3 * NVERT;
    const float* Xy = Xx + NVERT;

    // Two rows feed each output row: (r-1, r) interior; (0, 1) for r == 0.
    const int rA = (r >= 1) ? (r - 1) : 0;
    const int rB = (r >= 1) ? r : 1;

    const float4 xA = *(const float4*)(Xx + rA * G + c0);
    const float4 yA = *(const float4*)(Xy + rA * G + c0);
    const float4 xB = *(const float4*)(Xx + rB * G + c0);
    const float4 yB = *(const float4*)(Xy + rB * G + c0);

    // Left-neighbor scalars at column c0-1 (only thread 0 skips them).
    float xAm = 0.f, yAm = 0.f, xBm = 0.f, yBm = 0.f;
    if (c0 > 0) {
        xBm = Xx[rB * G + c0 - 1];
        yBm = Xy[rB * G + c0 - 1];
        if (r == 0) {
            xAm = Xx[rA * G + c0 - 1];
            yAm = Xy[rA * G + c0 - 1];
        }
    }

    const float xa[5] = {xAm, xA.x, xA.y, xA.z, xA.w};
    const float ya[5] = {yAm, yA.x, yA.y, yA.z, yA.w};
    const float xb[5] = {xBm, xB.x, xB.y, xB.z, xB.w};
    const float yb[5] = {yBm, yB.x, yB.y, yB.z, yB.w};

    float o[4];
#pragma unroll
    for (int k = 0; k < 4; k++) {
        const int c = c0 + k;
        float e0x, e0y, e2x, e2y;
        if (r >= 1) {
            if (c >= 1) {
                // v0=(r-1,c), v1=(r,c-1), v2=(r,c)
                e0x = xb[k] - xa[k + 1];  e0y = yb[k] - ya[k + 1];
                e2x = xb[k] - xb[k + 1];  e2y = yb[k] - yb[k + 1];
            } else {
                // c==0: v0=(r-1,1), v1=(r,0), v2=(r,1)
                e0x = xb[1] - xa[2];  e0y = yb[1] - ya[2];
                e2x = xb[1] - xb[2];  e2y = yb[1] - yb[2];
            }
        } else {
            if (c >= 1) {
                // r==0: v0=(0,c-1), v1=(1,c-1), v2=(0,c)
                e0x = xb[k] - xa[k];      e0y = yb[k] - ya[k];
                e2x = xb[k] - xa[k + 1];  e2y = yb[k] - ya[k + 1];
            } else {
                // (0,0): v0=(0,0), v1=(1,0), v2=(0,1)
                e0x = xb[1] - xa[1];  e0y = yb[1] - ya[1];
                e2x = xb[1] - xa[2];  e2y = yb[1] - ya[2];
            }
        }
        const float tnz = e0x * e2y - e0y * e2x;
        o[k] = (tnz >= 0.0f) ? 0.0f : 1.0f;
    }

    const float4 ov = make_float4(o[0], o[1], o[2], o[3]);
    float* ob = out + (size_t)b * 3 * NVERT + (size_t)r * G + c0;
    *(float4*)(ob)             = ov;
    *(float4*)(ob + NVERT)     = ov;
    *(float4*)(ob + 2 * NVERT) = ov;
}

extern "C" void kernel_launch(void* const* d_in, const int* in_sizes, int n_in,
                              void* d_out, int out_size) {
    const float* X = (const float*)d_in[0];   // (4, 3, 512*512) float32
    // d_in[1] = faces (int32) — implicit in the grid structure, unused.
    float* out = (float*)d_out;               // (4, 3, 512, 512) float32

    dim3 block(128, 1, 1);
    dim3 grid(G, 4, 1);
    vis_mask_kernel<<<grid, block>>>(X, out);
}

// round 16
// speedup vs baseline: 1.6232x; 1.0048x over previous
#include <cuda_runtime.h>

#define G 512
#define NVERT (G * G)

// Per vertex, the reference's last-write-wins scatter leaves exactly one face's
// angle-weighted normal. In every branch the angle weight is >= 0, so
// sign(normal_z) == sign(cross(e0, e2).z) == sign(e0x*e2y - e0y*e2x),
// which needs only the x,y channels of X. Output = (tnz >= 0) ? 0 : 1 on all
// 3 channels.
//
// FINAL kernel == R1: best of 9 measured structural variants. Identical
// source benched {6.56, 8.13, 10.75, 8.51, 6.66} us (ncu 6.18-9.25 us, HBM
// 908-1325 GB/s on identical SASS): environment noise dominates. At
// favorable clocks the kernel sits within ~5% of its floor (8 MB reads +
// 12 MB writes at the LTS ceiling + fixed launch/ramp overhead); no pipe
// exceeds 23% and 13 rounds of structural perturbation found no improvement.
//
// 4 columns per thread (float4), 128 threads per row, one block per (row, batch).
__global__ void __launch_bounds__(128) vis_mask_kernel(const float* __restrict__ X,
                                                       float* __restrict__ out) {
    const int c0 = threadIdx.x << 2;   // 128 * 4 = 512 columns
    const int r  = blockIdx.x;
    const int b  = blockIdx.y;

    const float* Xx = X + (size_t)b * 3 * NVERT;
    const float* Xy = Xx + NVERT;

    // Two rows feed each output row: (r-1, r) interior; (0, 1) for r == 0.
    const int rA = (r >= 1) ? (r - 1) : 0;
    const int rB = (r >= 1) ? r : 1;

    const float4 xA = *(const float4*)(Xx + rA * G + c0);
    const float4 yA = *(const float4*)(Xy + rA * G + c0);
    const float4 xB = *(const float4*)(Xx + rB * G + c0);
    const float4 yB = *(const float4*)(Xy + rB * G + c0);

    // Left-neighbor scalars at column c0-1 (only thread 0 skips them).
    float xAm = 0.f, yAm = 0.f, xBm = 0.f, yBm = 0.f;
    if (c0 > 0) {
        xBm = Xx[rB * G + c0 - 1];
        yBm = Xy[rB * G + c0 - 1];
        if (r == 0) {
            xAm = Xx[rA * G + c0 - 1];
            yAm = Xy[rA * G + c0 - 1];
        }
    }

    const float xa[5] = {xAm, xA.x, xA.y, xA.z, xA.w};
    const float ya[5] = {yAm, yA.x, yA.y, yA.z, yA.w};
    const float xb[5] = {xBm, xB.x, xB.y, xB.z, xB.w};
    const float yb[5] = {yBm, yB.x, yB.y, yB.z, yB.w};

    float o[4];
#pragma unroll
    for (int k = 0; k < 4; k++) {
        const int c = c0 + k;
        float e0x, e0y, e2x, e2y;
        if (r >= 1) {
            if (c >= 1) {
                // v0=(r-1,c), v1=(r,c-1), v2=(r,c)
                e0x = xb[k] - xa[k + 1];  e0y = yb[k] - ya[k + 1];
                e2x = xb[k] - xb[k + 1];  e2y = yb[k] - yb[k + 1];
            } else {
                // c==0: v0=(r-1,1), v1=(r,0), v2=(r,1)
                e0x = xb[1] - xa[2];  e0y = yb[1] - ya[2];
                e2x = xb[1] - xb[2];  e2y = yb[1] - yb[2];
            }
        } else {
            if (c >= 1) {
                // r==0: v0=(0,c-1), v1=(1,c-1), v2=(0,c)
                e0x = xb[k] - xa[k];      e0y = yb[k] - ya[k];
                e2x = xb[k] - xa[k + 1];  e2y = yb[k] - ya[k + 1];
            } else {
                // (0,0): v0=(0,0), v1=(1,0), v2=(0,1)
                e0x = xb[1] - xa[1];  e0y = yb[1] - ya[1];
                e2x = xb[1] - xa[2];  e2y = yb[1] - ya[2];
            }
        }
        const float tnz = e0x * e2y - e0y * e2x;
        o[k] = (tnz >= 0.0f) ? 0.0f : 1.0f;
    }

    const float4 ov = make_float4(o[0], o[1], o[2], o[3]);
    float* ob = out + (size_t)b * 3 * NVERT + (size_t)r * G + c0;
    *(float4*)(ob)             = ov;
    *(float4*)(ob + NVERT)     = ov;
    *(float4*)(ob + 2 * NVERT) = ov;
}

extern "C" void kernel_launch(void* const* d_in, const int* in_sizes, int n_in,
                              void* d_out, int out_size) {
    const float* X = (const float*)d_in[0];   // (4, 3, 512*512) float32
    // d_in[1] = faces (int32) — implicit in the grid structure, unused.
    float* out = (float*)d_out;               // (4, 3, 512, 512) float32

    dim3 block(128, 1, 1);
    dim3 grid(G, 4, 1);
    vis_mask_kernel<<<grid, block>>>(X, out);
}